// round 4
// baseline (speedup 1.0000x reference)
#include <cuda_runtime.h>
#include <cuda_bf16.h>
#include <cstdint>

// ---------------------------------------------------------------------------
// RingNet restructured: SAT (L2-resident) -> fused [feature-gen + GEMM1] ->
// ReLU -> GEMM2. bf16 hi/lo 3-product via mma.sync (HMMA), cp.async pipelined.
// A tiles are computed on the fly from the SAT inside the GEMM1 mainloop.
// ---------------------------------------------------------------------------

namespace {
constexpr int Bn = 4, Cn = 96, Hn = 128, Wn = 128;
constexpr int HWn = Hn * Wn;           // 16384
constexpr int Mtot = Bn * HWn;         // 65536
constexpr int K1 = 1248, N1 = 512, N2 = 96;
constexpr int KKP = 1280;              // K1 padded to mult of 32
constexpr int SATR = 129, SATC = 132;
constexpr float BN_EPS = 1e-5f;
}

// -------------------- device scratch ----------------------------------------
__device__ float         g_sat[(size_t)Bn * Cn * SATR * SATC];   // 26 MB (L2)
__device__ __nv_bfloat16 g_h1_hi[(size_t)Mtot * N1];             // [m][n]
__device__ __nv_bfloat16 g_h1_lo[(size_t)Mtot * N1];
__device__ __nv_bfloat16 g_W1h[N1 * KKP], g_W1l[N1 * KKP];
__device__ __nv_bfloat16 g_W2h[N2 * N1],  g_W2l[N2 * N1];
__device__ float         g_b1f[N1], g_b2f[N2];

// -------------------- helpers ------------------------------------------------
__device__ __forceinline__ uint32_t smem_u32(const void* p) {
    uint32_t a;
    asm("{ .reg .u64 t; cvta.to.shared.u64 t, %1; cvt.u32.u64 %0, t; }" : "=r"(a) : "l"(p));
    return a;
}
__device__ __forceinline__ void cpa16(uint32_t dst, const void* src) {
    asm volatile("cp.async.cg.shared.global [%0], [%1], 16;" :: "r"(dst), "l"(src));
}
__device__ __forceinline__ void mma16816(float* c, const uint32_t* a, const uint32_t* b) {
    asm volatile(
        "mma.sync.aligned.m16n8k16.row.col.f32.bf16.bf16.f32 "
        "{%0,%1,%2,%3},{%4,%5,%6,%7},{%8,%9},{%0,%1,%2,%3};\n"
        : "+f"(c[0]), "+f"(c[1]), "+f"(c[2]), "+f"(c[3])
        : "r"(a[0]), "r"(a[1]), "r"(a[2]), "r"(a[3]), "r"(b[0]), "r"(b[1]));
}
__device__ __forceinline__ uint32_t pack_hi(float v0, float v1) {
    __nv_bfloat162 h; h.x = __float2bfloat16(v0); h.y = __float2bfloat16(v1);
    return *(uint32_t*)&h;
}
__device__ __forceinline__ uint32_t pack_lo(float v0, float v1, uint32_t hi) {
    __nv_bfloat162 h = *(__nv_bfloat162*)&hi;
    __nv_bfloat162 l;
    l.x = __float2bfloat16(v0 - __bfloat162float(h.x));
    l.y = __float2bfloat16(v1 - __bfloat162float(h.y));
    return *(uint32_t*)&l;
}

// -------------------- weight folding (one launch) ----------------------------
__global__ void k_folds(const float* __restrict__ W1, const float* __restrict__ b1,
                        const float* __restrict__ ga1, const float* __restrict__ be1,
                        const float* __restrict__ mu1, const float* __restrict__ va1,
                        const float* __restrict__ W2, const float* __restrict__ b2,
                        const float* __restrict__ ga2, const float* __restrict__ be2,
                        const float* __restrict__ mu2, const float* __restrict__ va2) {
    int tid = threadIdx.x;
    float part = 0.f;
    if (blockIdx.x < N1) {
        int o = blockIdx.x;
        for (int c = tid; c < KKP; c += 256) {
            float wb = 0.f;
            if (c < K1) {
                float s  = ga1[c] * rsqrtf(va1[c] + BN_EPS);
                float w  = W1[(size_t)o * K1 + c];
                part += w * (be1[c] - mu1[c] * s);
                wb = w * s;
                if (c < K1 - 96) {
                    float s2 = ga1[c + 96] * rsqrtf(va1[c + 96] + BN_EPS);
                    wb -= W1[(size_t)o * K1 + c + 96] * s2;
                }
            }
            __nv_bfloat16 hi = __float2bfloat16(wb);
            g_W1h[(size_t)o * KKP + c] = hi;
            g_W1l[(size_t)o * KKP + c] = __float2bfloat16(wb - __bfloat162float(hi));
        }
    } else {
        int o = blockIdx.x - N1;
        for (int c = tid; c < N1; c += 256) {
            float s  = ga2[c] * rsqrtf(va2[c] + BN_EPS);
            float w  = W2[(size_t)o * N1 + c];
            part += w * (be2[c] - mu2[c] * s);
            float wf = w * s;
            __nv_bfloat16 hi = __float2bfloat16(wf);
            g_W2h[(size_t)o * N1 + c] = hi;
            g_W2l[(size_t)o * N1 + c] = __float2bfloat16(wf - __bfloat162float(hi));
        }
    }
    __shared__ float red[256];
    red[tid] = part; __syncthreads();
    for (int s = 128; s > 0; s >>= 1) { if (tid < s) red[tid] += red[tid + s]; __syncthreads(); }
    if (tid == 0) {
        if (blockIdx.x < N1) g_b1f[blockIdx.x] = b1[blockIdx.x] + red[0];
        else g_b2f[blockIdx.x - N1] = b2[blockIdx.x - N1] + red[0];
    }
}

// -------------------- summed-area tables -------------------------------------
__global__ void k_sat_rows(const float* __restrict__ x) {
    int idx = blockIdx.x * blockDim.x + threadIdx.x;
    if (idx >= Bn * Cn * SATR) return;
    int img = idx / SATR, r = idx % SATR;
    float* S = g_sat + (size_t)img * SATR * SATC;
    if (r == 0) { for (int cx = 0; cx <= 128; cx++) S[cx] = 0.f; }
    else {
        const float* row = x + (size_t)img * HWn + (size_t)(r - 1) * Wn;
        float* Sr = S + (size_t)r * SATC;
        Sr[0] = 0.f;
        float acc = 0.f;
        for (int xx = 0; xx < Wn; xx++) { acc += row[xx]; Sr[xx + 1] = acc; }
    }
}
__global__ void k_sat_cols() {
    int idx = blockIdx.x * blockDim.x + threadIdx.x;
    if (idx >= Bn * Cn * SATR) return;
    int img = idx / SATR, cc = idx % SATR;
    float* S = g_sat + (size_t)img * SATR * SATC;
    float acc = 0.f;
    for (int r = 1; r <= 128; r++) {
        acc += S[(size_t)r * SATC + cc];
        S[(size_t)r * SATC + cc] = acc;
    }
}

// -------------------- fused feature-gen + GEMM1 ------------------------------
// Per CTA: C[128 m, 256 n]. A tile computed from SAT/x into smem (hi/lo bf16),
// B via cp.async. 512 threads, warps 2m x 8n, warp tile 64m x 32n.
__global__ void __launch_bounds__(512, 1) k_gemm1(const float* __restrict__ x) {
    constexpr int BN   = 256;
    constexpr int RS   = 80;
    constexpr int A_TS = 128 * RS;                // 10240
    constexpr int B_TS = BN * RS;                 // 20480
    constexpr int SS   = 2 * A_TS + 2 * B_TS;     // 61440
    constexpr int NC   = KKP / 32;                // 40

    extern __shared__ char smem[];
    float* s_bias = (float*)(smem + 2 * SS);
    uint32_t sb = smem_u32(smem);

    int tid = threadIdx.x, wid = tid >> 5, lane = tid & 31;
    int g = lane >> 2, t = lane & 3;
    int wm = (wid & 1) * 64, wn = (wid >> 1) * 32;
    int m0 = blockIdx.x * 128, n0 = blockIdx.y * BN;

    // per-thread pixel for A-tile generation
    int m_in = tid & 127, kq = tid >> 7;          // kq 0..3
    int m = m0 + m_in;
    int b = m >> 14, pix = m & (HWn - 1), y = pix >> 7, xx = pix & 127;

    for (int i = tid; i < BN; i += 512) s_bias[i] = g_b1f[n0 + i];

    float acc[4][4][4];
    #pragma unroll
    for (int mt = 0; mt < 4; mt++)
        #pragma unroll
        for (int nt = 0; nt < 4; nt++)
            #pragma unroll
            for (int r = 0; r < 4; r++) acc[mt][nt][r] = 0.f;

    auto stage = [&](int c, int s) {
        uint32_t base = sb + s * SS;
        int kb = c * 32;
        // B: cp.async (hi then lo), BN*8 = 2048 16B-units
        #pragma unroll
        for (int i = tid; i < 2048; i += 512) {
            int hl = (i >= 1024);
            int q = i & 1023, r = q >> 2, u = q & 3;
            const __nv_bfloat16* src = (hl ? g_W1l : g_W1h)
                                     + (size_t)(n0 + r) * KKP + kb + u * 8;
            cpa16(base + 2 * A_TS + hl * B_TS + r * RS + u * 16, src);
        }
        asm volatile("cp.async.commit_group;" ::: "memory");
        // A: compute 8 k-values for this thread's pixel from SAT / x
        char* sA = smem + s * SS;
        #pragma unroll
        for (int i = 0; i < 8; i += 2) {
            float v[2];
            #pragma unroll
            for (int q = 0; q < 2; q++) {
                int k = kb + kq * 8 + i + q;
                float vv = 0.f;
                if (k < K1) {
                    int j = k / 96, cc = k - j * 96;
                    if (j == 0) {
                        vv = x[(size_t)(b * Cn + cc) * HWn + pix];
                    } else {
                        const float* S = g_sat + (size_t)(b * Cn + cc) * SATR * SATC;
                        int rlo = max(y - j, 0),  rhi = min(y + j + 1, 128);
                        int clo = max(xx - j, 0), chi = min(xx + j + 1, 128);
                        vv = S[(size_t)rhi * SATC + chi] - S[(size_t)rlo * SATC + chi]
                           - S[(size_t)rhi * SATC + clo] + S[(size_t)rlo * SATC + clo];
                    }
                }
                v[q] = vv;
            }
            uint32_t hi = pack_hi(v[0], v[1]);
            uint32_t lo = pack_lo(v[0], v[1], hi);
            int off = m_in * RS + (kq * 8 + i) * 2;
            *(uint32_t*)(sA + off)        = hi;
            *(uint32_t*)(sA + A_TS + off) = lo;
        }
    };

    stage(0, 0);
    for (int c = 0; c < NC; c++) {
        int s = c & 1;
        if (c + 1 < NC) {
            stage(c + 1, s ^ 1);
            asm volatile("cp.async.wait_group 1;" ::: "memory");
        } else {
            asm volatile("cp.async.wait_group 0;" ::: "memory");
        }
        __syncthreads();

        const char* base = smem + s * SS;
        #pragma unroll
        for (int ks = 0; ks < 2; ks++) {
            int ck = ks * 32;
            uint32_t ah[4][4], al[4][4], bh[4][2], bl[4][2];
            #pragma unroll
            for (int mt = 0; mt < 4; mt++) {
                const char* p = base + (wm + mt * 16 + g) * RS + ck + t * 4;
                ah[mt][0] = *(const uint32_t*)p;
                ah[mt][1] = *(const uint32_t*)(p + 8 * RS);
                ah[mt][2] = *(const uint32_t*)(p + 16);
                ah[mt][3] = *(const uint32_t*)(p + 8 * RS + 16);
                al[mt][0] = *(const uint32_t*)(p + A_TS);
                al[mt][1] = *(const uint32_t*)(p + A_TS + 8 * RS);
                al[mt][2] = *(const uint32_t*)(p + A_TS + 16);
                al[mt][3] = *(const uint32_t*)(p + A_TS + 8 * RS + 16);
            }
            #pragma unroll
            for (int nt = 0; nt < 4; nt++) {
                const char* p = base + 2 * A_TS + (wn + nt * 8 + g) * RS + ck + t * 4;
                bh[nt][0] = *(const uint32_t*)p;
                bh[nt][1] = *(const uint32_t*)(p + 16);
                bl[nt][0] = *(const uint32_t*)(p + B_TS);
                bl[nt][1] = *(const uint32_t*)(p + B_TS + 16);
            }
            #pragma unroll
            for (int mt = 0; mt < 4; mt++)
                #pragma unroll
                for (int nt = 0; nt < 4; nt++) {
                    mma16816(acc[mt][nt], ah[mt], bh[nt]);
                    mma16816(acc[mt][nt], ah[mt], bl[nt]);
                    mma16816(acc[mt][nt], al[mt], bh[nt]);
                }
        }
        __syncthreads();
    }

    // epilogue: relu(v + bias) -> h1 hi/lo
    #pragma unroll
    for (int mt = 0; mt < 4; mt++) {
        int mr = m0 + wm + mt * 16 + g;
        #pragma unroll
        for (int nt = 0; nt < 4; nt++) {
            int ncl = wn + nt * 8 + 2 * t;
            int nc  = n0 + ncl;
            #pragma unroll
            for (int h = 0; h < 2; h++) {
                int mrow = mr + h * 8;
                float v0 = fmaxf(acc[mt][nt][2 * h]     + s_bias[ncl], 0.f);
                float v1 = fmaxf(acc[mt][nt][2 * h + 1] + s_bias[ncl + 1], 0.f);
                uint32_t hi = pack_hi(v0, v1);
                uint32_t lo = pack_lo(v0, v1, hi);
                *(uint32_t*)(g_h1_hi + (size_t)mrow * N1 + nc) = hi;
                *(uint32_t*)(g_h1_lo + (size_t)mrow * N1 + nc) = lo;
            }
        }
    }
}

// -------------------- GEMM2 (h1 -> out) --------------------------------------
// C[128 m, 96 n], 256 threads, warps 2m x 4n, warp tile 64m x 24n.
__global__ void __launch_bounds__(256, 1) k_gemm2(float* __restrict__ dout) {
    constexpr int KK = N1, BN = 96, NT = 3;
    constexpr int RS = 80;
    constexpr int A_TS = 128 * RS, B_TS = BN * RS;
    constexpr int SS = 2 * A_TS + 2 * B_TS;
    constexpr int NC = KK / 32;

    extern __shared__ char smem[];
    float* s_bias = (float*)(smem + 2 * SS);
    uint32_t sb = smem_u32(smem);

    int tid = threadIdx.x, wid = tid >> 5, lane = tid & 31;
    int g = lane >> 2, t = lane & 3;
    int wm = (wid & 1) * 64, wn = (wid >> 1) * (NT * 8);
    int m0 = blockIdx.x * 128;

    for (int i = tid; i < BN; i += 256) s_bias[i] = g_b2f[i];

    float acc[4][NT][4];
    #pragma unroll
    for (int mt = 0; mt < 4; mt++)
        #pragma unroll
        for (int nt = 0; nt < NT; nt++)
            #pragma unroll
            for (int r = 0; r < 4; r++) acc[mt][nt][r] = 0.f;

    auto stage = [&](int c, int s) {
        uint32_t base = sb + s * SS;
        int kb = c * 32;
        #pragma unroll
        for (int i = tid; i < 1024 + BN * 8; i += 256) {
            const __nv_bfloat16* src;
            uint32_t doff;
            if (i < 1024) {
                int hl = (i >= 512);
                int r = (i & 511) >> 2, u = i & 3;
                src = (hl ? g_h1_lo : g_h1_hi) + (size_t)(m0 + r) * KK + kb + u * 8;
                doff = hl * A_TS + r * RS + u * 16;
            } else {
                int jx = i - 1024;
                int hl = (jx >= BN * 4);
                int q = hl ? jx - BN * 4 : jx;
                int r = q >> 2, u = q & 3;
                src = (hl ? g_W2l : g_W2h) + (size_t)r * KK + kb + u * 8;
                doff = 2 * A_TS + hl * B_TS + r * RS + u * 16;
            }
            cpa16(base + doff, src);
        }
        asm volatile("cp.async.commit_group;" ::: "memory");
    };

    stage(0, 0);
    for (int c = 0; c < NC; c++) {
        int s = c & 1;
        if (c + 1 < NC) {
            stage(c + 1, s ^ 1);
            asm volatile("cp.async.wait_group 1;" ::: "memory");
        } else {
            asm volatile("cp.async.wait_group 0;" ::: "memory");
        }
        __syncthreads();

        const char* base = smem + s * SS;
        #pragma unroll
        for (int ks = 0; ks < 2; ks++) {
            int ck = ks * 32;
            uint32_t ah[4][4], al[4][4], bh[NT][2], bl[NT][2];
            #pragma unroll
            for (int mt = 0; mt < 4; mt++) {
                const char* p = base + (wm + mt * 16 + g) * RS + ck + t * 4;
                ah[mt][0] = *(const uint32_t*)p;
                ah[mt][1] = *(const uint32_t*)(p + 8 * RS);
                ah[mt][2] = *(const uint32_t*)(p + 16);
                ah[mt][3] = *(const uint32_t*)(p + 8 * RS + 16);
                al[mt][0] = *(const uint32_t*)(p + A_TS);
                al[mt][1] = *(const uint32_t*)(p + A_TS + 8 * RS);
                al[mt][2] = *(const uint32_t*)(p + A_TS + 16);
                al[mt][3] = *(const uint32_t*)(p + A_TS + 8 * RS + 16);
            }
            #pragma unroll
            for (int nt = 0; nt < NT; nt++) {
                const char* p = base + 2 * A_TS + (wn + nt * 8 + g) * RS + ck + t * 4;
                bh[nt][0] = *(const uint32_t*)p;
                bh[nt][1] = *(const uint32_t*)(p + 16);
                bl[nt][0] = *(const uint32_t*)(p + B_TS);
                bl[nt][1] = *(const uint32_t*)(p + B_TS + 16);
            }
            #pragma unroll
            for (int mt = 0; mt < 4; mt++)
                #pragma unroll
                for (int nt = 0; nt < NT; nt++) {
                    mma16816(acc[mt][nt], ah[mt], bh[nt]);
                    mma16816(acc[mt][nt], ah[mt], bl[nt]);
                    mma16816(acc[mt][nt], al[mt], bh[nt]);
                }
        }
        __syncthreads();
    }

    #pragma unroll
    for (int mt = 0; mt < 4; mt++) {
        int mr = m0 + wm + mt * 16 + g;
        #pragma unroll
        for (int nt = 0; nt < NT; nt++) {
            int nc = wn + nt * 8 + 2 * t;
            #pragma unroll
            for (int h = 0; h < 2; h++) {
                int mrow = mr + h * 8;
                int b = mrow >> 14, pix = mrow & (HWn - 1);
                dout[(size_t)(b * N2 + nc) * HWn + pix]     = acc[mt][nt][2 * h]     + s_bias[nc];
                dout[(size_t)(b * N2 + nc + 1) * HWn + pix] = acc[mt][nt][2 * h + 1] + s_bias[nc + 1];
            }
        }
    }
}

// -------------------- launch ------------------------------------------------
extern "C" void kernel_launch(void* const* d_in, const int* in_sizes, int n_in,
                              void* d_out, int out_size) {
    (void)in_sizes; (void)n_in; (void)out_size;
    const float* x   = (const float*)d_in[0];
    const float* g1  = (const float*)d_in[1];
    const float* be1 = (const float*)d_in[2];
    const float* mu1 = (const float*)d_in[3];
    const float* va1 = (const float*)d_in[4];
    const float* W1  = (const float*)d_in[5];
    const float* b1  = (const float*)d_in[6];
    const float* g2  = (const float*)d_in[7];
    const float* be2 = (const float*)d_in[8];
    const float* mu2 = (const float*)d_in[9];
    const float* va2 = (const float*)d_in[10];
    const float* W2  = (const float*)d_in[11];
    const float* b2  = (const float*)d_in[12];

    constexpr int S1 = 2 * (2 * 128 * 80 + 2 * 256 * 80) + 256 * 4;   // 123904
    constexpr int S2 = 2 * (2 * 128 * 80 + 2 * 96 * 80) + 96 * 4;     //  72064
    cudaFuncSetAttribute(k_gemm1, cudaFuncAttributeMaxDynamicSharedMemorySize, S1);
    cudaFuncSetAttribute(k_gemm2, cudaFuncAttributeMaxDynamicSharedMemorySize, S2);

    k_folds<<<N1 + N2, 256>>>(W1, b1, g1, be1, mu1, va1, W2, b2, g2, be2, mu2, va2);

    int nsat = Bn * Cn * SATR;
    k_sat_rows<<<(nsat + 127) / 128, 128>>>(x);
    k_sat_cols<<<(nsat + 127) / 128, 128>>>();

    k_gemm1<<<dim3(Mtot / 128, N1 / 256), 512, S1>>>(x);
    k_gemm2<<<dim3(Mtot / 128, 1), 256, S2>>>((float*)d_out);
}

// round 5
// speedup vs baseline: 1.9367x; 1.9367x over previous
#include <cuda_runtime.h>
#include <cuda_fp16.h>
#include <cstdint>

// ---------------------------------------------------------------------------
// RingNet: SAT box features -> folded GEMM1 -> ReLU -> folded GEMM2.
// GEMMs: A single fp16, B split hi/lo fp16, 2 HMMA products per tile
// (error ~= A fp16 quantization ~3e-4 per GEMM). ldmatrix fragment loads,
// cp.async double-buffered, 64x64 warp tiles.
// ---------------------------------------------------------------------------

namespace {
constexpr int Bn = 4, Cn = 96, Hn = 128, Wn = 128;
constexpr int HWn = Hn * Wn;           // 16384
constexpr int Mtot = Bn * HWn;         // 65536
constexpr int K1 = 1248, N1 = 512, N2 = 96;
constexpr int KKP = 1280;
constexpr int SATR = 129, SATC = 132;
constexpr float BN_EPS = 1e-5f;
}

// -------------------- device scratch ----------------------------------------
__device__ float  g_sat[(size_t)Bn * Cn * SATR * SATC];    // 26 MB
__device__ __half g_phi[(size_t)KKP * Mtot];               // [k][m] 168 MB
__device__ __half g_h1[(size_t)Mtot * N1];                 // [m][n]  67 MB
__device__ __half g_W1h[N1 * KKP], g_W1l[N1 * KKP];
__device__ __half g_W2h[N2 * N1],  g_W2l[N2 * N1];
__device__ float  g_b1f[N1], g_b2f[N2];

// -------------------- helpers ------------------------------------------------
__device__ __forceinline__ uint32_t smem_u32(const void* p) {
    uint32_t a;
    asm("{ .reg .u64 t; cvta.to.shared.u64 t, %1; cvt.u32.u64 %0, t; }" : "=r"(a) : "l"(p));
    return a;
}
__device__ __forceinline__ void cpa16(uint32_t dst, const void* src) {
    asm volatile("cp.async.cg.shared.global [%0], [%1], 16;" :: "r"(dst), "l"(src));
}
__device__ __forceinline__ void mma_h(float* c, const uint32_t* a, const uint32_t* b) {
    asm volatile(
        "mma.sync.aligned.m16n8k16.row.col.f32.f16.f16.f32 "
        "{%0,%1,%2,%3},{%4,%5,%6,%7},{%8,%9},{%0,%1,%2,%3};\n"
        : "+f"(c[0]), "+f"(c[1]), "+f"(c[2]), "+f"(c[3])
        : "r"(a[0]), "r"(a[1]), "r"(a[2]), "r"(a[3]), "r"(b[0]), "r"(b[1]));
}
__device__ __forceinline__ void ldsm4(uint32_t& a, uint32_t& b, uint32_t& c, uint32_t& d,
                                      uint32_t addr) {
    asm volatile("ldmatrix.sync.aligned.m8n8.x4.shared.b16 {%0,%1,%2,%3},[%4];"
        : "=r"(a), "=r"(b), "=r"(c), "=r"(d) : "r"(addr));
}
__device__ __forceinline__ void ldsm4t(uint32_t& a, uint32_t& b, uint32_t& c, uint32_t& d,
                                       uint32_t addr) {
    asm volatile("ldmatrix.sync.aligned.m8n8.x4.trans.shared.b16 {%0,%1,%2,%3},[%4];"
        : "=r"(a), "=r"(b), "=r"(c), "=r"(d) : "r"(addr));
}

// -------------------- weight folding -----------------------------------------
__global__ void k_folds(const float* __restrict__ W1, const float* __restrict__ b1,
                        const float* __restrict__ ga1, const float* __restrict__ be1,
                        const float* __restrict__ mu1, const float* __restrict__ va1,
                        const float* __restrict__ W2, const float* __restrict__ b2,
                        const float* __restrict__ ga2, const float* __restrict__ be2,
                        const float* __restrict__ mu2, const float* __restrict__ va2) {
    int tid = threadIdx.x;
    float part = 0.f;
    if (blockIdx.x < N1) {
        int o = blockIdx.x;
        for (int c = tid; c < KKP; c += 256) {
            float wb = 0.f;
            if (c < K1) {
                float s = ga1[c] * rsqrtf(va1[c] + BN_EPS);
                float w = W1[(size_t)o * K1 + c];
                part += w * (be1[c] - mu1[c] * s);
                wb = w * s;
                if (c < K1 - 96) {
                    float s2 = ga1[c + 96] * rsqrtf(va1[c + 96] + BN_EPS);
                    wb -= W1[(size_t)o * K1 + c + 96] * s2;
                }
            }
            __half hi = __float2half_rn(wb);
            g_W1h[(size_t)o * KKP + c] = hi;
            g_W1l[(size_t)o * KKP + c] = __float2half_rn(wb - __half2float(hi));
        }
    } else {
        int o = blockIdx.x - N1;
        for (int c = tid; c < N1; c += 256) {
            float s = ga2[c] * rsqrtf(va2[c] + BN_EPS);
            float w = W2[(size_t)o * N1 + c];
            part += w * (be2[c] - mu2[c] * s);
            float wf = w * s;
            __half hi = __float2half_rn(wf);
            g_W2h[(size_t)o * N1 + c] = hi;
            g_W2l[(size_t)o * N1 + c] = __float2half_rn(wf - __half2float(hi));
        }
    }
    __shared__ float red[256];
    red[tid] = part; __syncthreads();
    for (int s = 128; s > 0; s >>= 1) { if (tid < s) red[tid] += red[tid + s]; __syncthreads(); }
    if (tid == 0) {
        if (blockIdx.x < N1) g_b1f[blockIdx.x] = b1[blockIdx.x] + red[0];
        else g_b2f[blockIdx.x - N1] = b2[blockIdx.x - N1] + red[0];
    }
}

// -------------------- summed-area tables --------------------------------------
__global__ void k_sat_rows(const float* __restrict__ x) {
    int idx = blockIdx.x * blockDim.x + threadIdx.x;
    if (idx >= Bn * Cn * SATR) return;
    int img = idx / SATR, r = idx % SATR;
    float* S = g_sat + (size_t)img * SATR * SATC;
    if (r == 0) { for (int cx = 0; cx <= 128; cx++) S[cx] = 0.f; }
    else {
        const float* row = x + (size_t)img * HWn + (size_t)(r - 1) * Wn;
        float* Sr = S + (size_t)r * SATC;
        Sr[0] = 0.f;
        float acc = 0.f;
        for (int xx = 0; xx < Wn; xx++) { acc += row[xx]; Sr[xx + 1] = acc; }
    }
}
__global__ void k_sat_cols() {
    int idx = blockIdx.x * blockDim.x + threadIdx.x;
    if (idx >= Bn * Cn * SATR) return;
    int img = idx / SATR, cc = idx % SATR;
    float* S = g_sat + (size_t)img * SATR * SATC;
    float acc = 0.f;
    for (int r = 1; r <= 128; r++) {
        acc += S[(size_t)r * SATC + cc];
        S[(size_t)r * SATC + cc] = acc;
    }
}

// -------------------- features: phi[k][m] single fp16 -------------------------
__global__ void k_features(const float* __restrict__ x) {
    int k = blockIdx.y;
    int j = k / 96, c = k - j * 96;
    int tid = threadIdx.x;
    int mb = blockIdx.x * 1024;
    #pragma unroll
    for (int it = 0; it < 2; it++) {
        int m = mb + it * 512 + tid * 2;
        float v0 = 0.f, v1 = 0.f;
        if (k < K1) {
            int b = m >> 14, pix = m & (HWn - 1);
            if (j == 0) {
                const float* p = x + (size_t)(b * Cn + c) * HWn + pix;
                v0 = p[0]; v1 = p[1];
            } else {
                const float* S = g_sat + (size_t)(b * Cn + c) * SATR * SATC;
                #pragma unroll
                for (int q = 0; q < 2; q++) {
                    int pp = pix + q;
                    int y = pp >> 7, xx = pp & 127;
                    int rlo = max(y - j, 0),  rhi = min(y + j + 1, 128);
                    int clo = max(xx - j, 0), chi = min(xx + j + 1, 128);
                    float v = S[(size_t)rhi * SATC + chi] - S[(size_t)rlo * SATC + chi]
                            - S[(size_t)rhi * SATC + clo] + S[(size_t)rlo * SATC + clo];
                    if (q == 0) v0 = v; else v1 = v;
                }
            }
        }
        *(__half2*)(g_phi + (size_t)k * Mtot + m) = __floats2half2_rn(v0, v1);
    }
}

// -------------------- GEMM1: C[128m, 256n], 8 warps, warp tile 64x64 ----------
__global__ void __launch_bounds__(256, 1) k_gemm1() {
    constexpr int A_RS = 272, A_TS = 32 * A_RS;      // [k][m] rows: 256B data +16
    constexpr int B_RS = 80,  B_TS = 256 * B_RS;     // [n][k] rows: 64B data +16
    constexpr int SS = A_TS + 2 * B_TS;              // 49664
    constexpr int NC = KKP / 32;                     // 40

    extern __shared__ char smem[];
    float* s_bias = (float*)(smem + 2 * SS);
    uint32_t sb = smem_u32(smem);
    int tid = threadIdx.x, wid = tid >> 5, lane = tid & 31;
    int wm = (wid & 1) * 64, wn = (wid >> 1) * 64;
    int m0 = blockIdx.x * 128, n0 = blockIdx.y * 256;

    for (int i = tid; i < 256; i += 256) s_bias[i] = g_b1f[n0 + i];

    // ldmatrix lane offsets
    int grp = lane >> 3, r = lane & 7;
    // A trans ([k][m]): tiles (m0-7,k0-7)(m8-15,k0-7)(m0-7,k8-15)(m8-15,k8-15)
    uint32_t aoff0 = (uint32_t)((((grp >> 1) * 8) + r) * A_RS + wm * 2 + (grp & 1) * 16);
    // B ([n][k]): tiles (n0-7,k0-7)(n0-7,k8-15)(n8-15,k0-7)(n8-15,k8-15)
    uint32_t boff0 = (uint32_t)((wn + (grp >> 1) * 8 + r) * B_RS + (grp & 1) * 16);

    float acc[4][8][4];
    #pragma unroll
    for (int mt = 0; mt < 4; mt++)
        #pragma unroll
        for (int nt = 0; nt < 8; nt++)
            #pragma unroll
            for (int q = 0; q < 4; q++) acc[mt][nt][q] = 0.f;

    auto stage = [&](int c, int s) {
        uint32_t base = sb + s * SS;
        int kb = c * 32;
        #pragma unroll
        for (int i = tid; i < 512; i += 256) {              // A: 32 rows x 16 units
            int rr = i >> 4, u = i & 15;
            cpa16(base + rr * A_RS + u * 16, g_phi + (size_t)(kb + rr) * Mtot + m0 + u * 8);
        }
        #pragma unroll
        for (int i = tid; i < 1024; i += 256) {             // B hi+lo: 256 rows x 4 units
            int rr = i >> 2, u = i & 3;
            size_t so = (size_t)(n0 + rr) * KKP + kb + u * 8;
            cpa16(base + A_TS + rr * B_RS + u * 16, g_W1h + so);
            cpa16(base + A_TS + B_TS + rr * B_RS + u * 16, g_W1l + so);
        }
        asm volatile("cp.async.commit_group;" ::: "memory");
    };

    stage(0, 0);
    for (int c = 0; c < NC; c++) {
        int s = c & 1;
        if (c + 1 < NC) {
            stage(c + 1, s ^ 1);
            asm volatile("cp.async.wait_group 1;" ::: "memory");
        } else {
            asm volatile("cp.async.wait_group 0;" ::: "memory");
        }
        __syncthreads();

        uint32_t bA = sb + s * SS, bB = bA + A_TS;
        #pragma unroll
        for (int ks = 0; ks < 2; ks++) {
            uint32_t ah[4][4], bh[8][2], bl[8][2];
            #pragma unroll
            for (int mt = 0; mt < 4; mt++)
                ldsm4t(ah[mt][0], ah[mt][1], ah[mt][2], ah[mt][3],
                       bA + aoff0 + ks * (16 * A_RS) + mt * 32);
            #pragma unroll
            for (int p = 0; p < 4; p++) {
                uint32_t off = boff0 + p * (16 * B_RS) + ks * 32;
                ldsm4(bh[2*p][0], bh[2*p][1], bh[2*p+1][0], bh[2*p+1][1], bB + off);
                ldsm4(bl[2*p][0], bl[2*p][1], bl[2*p+1][0], bl[2*p+1][1], bB + B_TS + off);
            }
            #pragma unroll
            for (int mt = 0; mt < 4; mt++)
                #pragma unroll
                for (int nt = 0; nt < 8; nt++) {
                    mma_h(acc[mt][nt], ah[mt], bh[nt]);
                    mma_h(acc[mt][nt], ah[mt], bl[nt]);
                }
        }
        __syncthreads();
    }

    // epilogue: relu(v + bias) -> h1 single fp16 [m][N1]
    int g = lane >> 2, t = lane & 3;
    #pragma unroll
    for (int mt = 0; mt < 4; mt++) {
        int mr = m0 + wm + mt * 16 + g;
        #pragma unroll
        for (int nt = 0; nt < 8; nt++) {
            int ncl = wn + nt * 8 + 2 * t;
            #pragma unroll
            for (int h = 0; h < 2; h++) {
                int mrow = mr + h * 8;
                float v0 = fmaxf(acc[mt][nt][2 * h]     + s_bias[ncl], 0.f);
                float v1 = fmaxf(acc[mt][nt][2 * h + 1] + s_bias[ncl + 1], 0.f);
                *(__half2*)(g_h1 + (size_t)mrow * N1 + n0 + ncl) = __floats2half2_rn(v0, v1);
            }
        }
    }
}

// -------------------- GEMM2: C[128m, 96n], 8 warps 4m x 2n, tile 32x48 --------
__global__ void __launch_bounds__(256, 1) k_gemm2(float* __restrict__ dout) {
    constexpr int A_RS = 80, A_TS = 128 * A_RS;      // [m][k] rows 64B +16
    constexpr int B_RS = 80, B_TS = 96 * B_RS;
    constexpr int SS = A_TS + 2 * B_TS;              // 25600
    constexpr int NC = N1 / 32;                      // 16

    extern __shared__ char smem[];
    float* s_bias = (float*)(smem + 2 * SS);
    uint32_t sb = smem_u32(smem);
    int tid = threadIdx.x, wid = tid >> 5, lane = tid & 31;
    int wm = (wid & 3) * 32, wn = (wid >> 2) * 48;
    int m0 = blockIdx.x * 128;

    for (int i = tid; i < 96; i += 256) s_bias[i] = g_b2f[i];

    int grp = lane >> 3, r = lane & 7;
    // A non-trans ([m][k]): tiles (m0-7,k0)(m8-15,k0)(m0-7,k8)(m8-15,k8)
    uint32_t aoff0 = (uint32_t)((wm + (grp & 1) * 8 + r) * A_RS + (grp >> 1) * 16);
    uint32_t boff0 = (uint32_t)((wn + (grp >> 1) * 8 + r) * B_RS + (grp & 1) * 16);

    float acc[2][6][4];
    #pragma unroll
    for (int mt = 0; mt < 2; mt++)
        #pragma unroll
        for (int nt = 0; nt < 6; nt++)
            #pragma unroll
            for (int q = 0; q < 4; q++) acc[mt][nt][q] = 0.f;

    auto stage = [&](int c, int s) {
        uint32_t base = sb + s * SS;
        int kb = c * 32;
        #pragma unroll
        for (int i = tid; i < 512; i += 256) {              // A: 128 rows x 4 units
            int rr = i >> 2, u = i & 3;
            cpa16(base + rr * A_RS + u * 16, g_h1 + (size_t)(m0 + rr) * N1 + kb + u * 8);
        }
        #pragma unroll
        for (int i = tid; i < 384; i += 256) {              // B hi+lo: 96 rows x 4
            int rr = i >> 2, u = i & 3;
            size_t so = (size_t)rr * N1 + kb + u * 8;
            cpa16(base + A_TS + rr * B_RS + u * 16, g_W2h + so);
            cpa16(base + A_TS + B_TS + rr * B_RS + u * 16, g_W2l + so);
        }
        asm volatile("cp.async.commit_group;" ::: "memory");
    };

    stage(0, 0);
    for (int c = 0; c < NC; c++) {
        int s = c & 1;
        if (c + 1 < NC) {
            stage(c + 1, s ^ 1);
            asm volatile("cp.async.wait_group 1;" ::: "memory");
        } else {
            asm volatile("cp.async.wait_group 0;" ::: "memory");
        }
        __syncthreads();

        uint32_t bA = sb + s * SS, bB = bA + A_TS;
        #pragma unroll
        for (int ks = 0; ks < 2; ks++) {
            uint32_t ah[2][4], bh[6][2], bl[6][2];
            #pragma unroll
            for (int mt = 0; mt < 2; mt++)
                ldsm4(ah[mt][0], ah[mt][1], ah[mt][2], ah[mt][3],
                      bA + aoff0 + mt * (16 * A_RS) + ks * 32);
            #pragma unroll
            for (int p = 0; p < 3; p++) {
                uint32_t off = boff0 + p * (16 * B_RS) + ks * 32;
                ldsm4(bh[2*p][0], bh[2*p][1], bh[2*p+1][0], bh[2*p+1][1], bB + off);
                ldsm4(bl[2*p][0], bl[2*p][1], bl[2*p+1][0], bl[2*p+1][1], bB + B_TS + off);
            }
            #pragma unroll
            for (int mt = 0; mt < 2; mt++)
                #pragma unroll
                for (int nt = 0; nt < 6; nt++) {
                    mma_h(acc[mt][nt], ah[mt], bh[nt]);
                    mma_h(acc[mt][nt], ah[mt], bl[nt]);
                }
        }
        __syncthreads();
    }

    int g = lane >> 2, t = lane & 3;
    #pragma unroll
    for (int mt = 0; mt < 2; mt++) {
        int mr = m0 + wm + mt * 16 + g;
        #pragma unroll
        for (int nt = 0; nt < 6; nt++) {
            int nc = wn + nt * 8 + 2 * t;
            #pragma unroll
            for (int h = 0; h < 2; h++) {
                int mrow = mr + h * 8;
                int b = mrow >> 14, pix = mrow & (HWn - 1);
                dout[(size_t)(b * N2 + nc) * HWn + pix]     = acc[mt][nt][2 * h]     + s_bias[nc];
                dout[(size_t)(b * N2 + nc + 1) * HWn + pix] = acc[mt][nt][2 * h + 1] + s_bias[nc + 1];
            }
        }
    }
}

// -------------------- launch ------------------------------------------------
extern "C" void kernel_launch(void* const* d_in, const int* in_sizes, int n_in,
                              void* d_out, int out_size) {
    (void)in_sizes; (void)n_in; (void)out_size;
    const float* x   = (const float*)d_in[0];
    const float* g1  = (const float*)d_in[1];
    const float* be1 = (const float*)d_in[2];
    const float* mu1 = (const float*)d_in[3];
    const float* va1 = (const float*)d_in[4];
    const float* W1  = (const float*)d_in[5];
    const float* b1  = (const float*)d_in[6];
    const float* g2  = (const float*)d_in[7];
    const float* be2 = (const float*)d_in[8];
    const float* mu2 = (const float*)d_in[9];
    const float* va2 = (const float*)d_in[10];
    const float* W2  = (const float*)d_in[11];
    const float* b2  = (const float*)d_in[12];

    constexpr int S1 = 2 * (32 * 272 + 2 * 256 * 80) + 256 * 4;   // 100352
    constexpr int S2 = 2 * (128 * 80 + 2 * 96 * 80) + 96 * 4;     //  51584
    cudaFuncSetAttribute(k_gemm1, cudaFuncAttributeMaxDynamicSharedMemorySize, S1);
    cudaFuncSetAttribute(k_gemm2, cudaFuncAttributeMaxDynamicSharedMemorySize, S2);

    k_folds<<<N1 + N2, 256>>>(W1, b1, g1, be1, mu1, va1, W2, b2, g2, be2, mu2, va2);

    int nsat = Bn * Cn * SATR;
    k_sat_rows<<<(nsat + 127) / 128, 128>>>(x);
    k_sat_cols<<<(nsat + 127) / 128, 128>>>();

    k_features<<<dim3(Mtot / 1024, KKP), 256>>>(x);

    k_gemm1<<<dim3(Mtot / 128, N1 / 256), 256, S1>>>();
    k_gemm2<<<dim3(Mtot / 128, 1), 256, S2>>>((float*)d_out);
}

// round 6
// speedup vs baseline: 2.5271x; 1.3049x over previous
#include <cuda_runtime.h>
#include <cuda_fp16.h>
#include <cstdint>

// ---------------------------------------------------------------------------
// RingNet: SAT box features -> folded GEMM1 -> ReLU -> folded GEMM2.
// GEMM1: A single fp16 / B hi+lo fp16 (2 HMMA products), operands pre-packed
// into chunk-contiguous XOR-swizzled blocks, staged by cp.async.bulk into a
// 4-stage mbarrier ring. GEMM2: cp.async pipeline (small).
// ---------------------------------------------------------------------------

namespace {
constexpr int Bn = 4, Cn = 96, Hn = 128, Wn = 128;
constexpr int HWn = Hn * Wn;           // 16384
constexpr int Mtot = Bn * HWn;         // 65536
constexpr int K1 = 1248, N1 = 512, N2 = 96;
constexpr int NC1 = K1 / 32;           // 39 chunks, exact
constexpr int SATR = 129, SATC = 132;
constexpr float BN_EPS = 1e-5f;
constexpr int A_TS = 8192;             // 32k x 256B  (per mtile per chunk)
constexpr int B_TS = 32768;            // 256n x 128B (hi|lo interleaved)
constexpr int STG  = A_TS + B_TS;      // 40960 per stage
constexpr int NSTG = 4;
}

// -------------------- device scratch ----------------------------------------
__device__ float   g_sat[(size_t)Bn * Cn * SATR * SATC];            // 26 MB
__device__ uint8_t g_phiB[(size_t)(Mtot / 128) * NC1 * A_TS];       // 164 MB
__device__ uint8_t g_W1p[(size_t)NC1 * 2 * B_TS];                   // 2.5 MB
__device__ __half  g_h1[(size_t)Mtot * N1];                         // 67 MB
__device__ __half  g_W2h[N2 * N1], g_W2l[N2 * N1];
__device__ float   g_b1f[N1], g_b2f[N2];

// -------------------- helpers ------------------------------------------------
__device__ __forceinline__ uint32_t smem_u32(const void* p) {
    uint32_t a;
    asm("{ .reg .u64 t; cvta.to.shared.u64 t, %1; cvt.u32.u64 %0, t; }" : "=r"(a) : "l"(p));
    return a;
}
__device__ __forceinline__ void cpa16(uint32_t dst, const void* src) {
    asm volatile("cp.async.cg.shared.global [%0], [%1], 16;" :: "r"(dst), "l"(src));
}
__device__ __forceinline__ void bulk_g2s(uint32_t dst, const void* src, uint32_t bytes,
                                         uint32_t mbar) {
    asm volatile(
        "cp.async.bulk.shared::cluster.global.mbarrier::complete_tx::bytes [%0], [%1], %2, [%3];"
        :: "r"(dst), "l"(src), "r"(bytes), "r"(mbar) : "memory");
}
#define MBAR_INIT(a, n) \
    asm volatile("mbarrier.init.shared.b64 [%0], %1;" :: "r"(a), "r"((uint32_t)(n)) : "memory")
#define MBAR_EXPECT_TX(a, n) \
    asm volatile("mbarrier.arrive.expect_tx.shared.b64 _, [%0], %1;" \
        :: "r"(a), "r"((uint32_t)(n)) : "memory")
#define MBAR_WAIT(a, p) do { \
    uint32_t _m = (a), _p = (uint32_t)(p), _d; \
    asm volatile("{\n\t.reg .pred q;\n\t" \
        "mbarrier.try_wait.parity.acquire.cta.shared::cta.b64 q, [%1], %2;\n\t" \
        "selp.b32 %0, 1, 0, q;\n\t}" : "=r"(_d) : "r"(_m), "r"(_p) : "memory"); \
    if (!_d) { \
        asm volatile("{\n\t.reg .pred Q;\n\tWL_%=:\n\t" \
            "mbarrier.try_wait.parity.acquire.cta.shared::cta.b64 Q, [%0], %1, 0x989680;\n\t" \
            "@Q bra.uni WD_%=;\n\tbra.uni WL_%=;\n\tWD_%=:\n\t}" \
            :: "r"(_m), "r"(_p) : "memory"); \
    } } while (0)
__device__ __forceinline__ void mma_h(float* c, const uint32_t* a, const uint32_t* b) {
    asm volatile(
        "mma.sync.aligned.m16n8k16.row.col.f32.f16.f16.f32 "
        "{%0,%1,%2,%3},{%4,%5,%6,%7},{%8,%9},{%0,%1,%2,%3};\n"
        : "+f"(c[0]), "+f"(c[1]), "+f"(c[2]), "+f"(c[3])
        : "r"(a[0]), "r"(a[1]), "r"(a[2]), "r"(a[3]), "r"(b[0]), "r"(b[1]));
}
__device__ __forceinline__ void ldsm4(uint32_t& a, uint32_t& b, uint32_t& c, uint32_t& d,
                                      uint32_t addr) {
    asm volatile("ldmatrix.sync.aligned.m8n8.x4.shared.b16 {%0,%1,%2,%3},[%4];"
        : "=r"(a), "=r"(b), "=r"(c), "=r"(d) : "r"(addr));
}
__device__ __forceinline__ void ldsm4t(uint32_t& a, uint32_t& b, uint32_t& c, uint32_t& d,
                                       uint32_t addr) {
    asm volatile("ldmatrix.sync.aligned.m8n8.x4.trans.shared.b16 {%0,%1,%2,%3},[%4];"
        : "=r"(a), "=r"(b), "=r"(c), "=r"(d) : "r"(addr));
}

// -------------------- weight folding + packing -------------------------------
__global__ void k_folds(const float* __restrict__ W1, const float* __restrict__ b1,
                        const float* __restrict__ ga1, const float* __restrict__ be1,
                        const float* __restrict__ mu1, const float* __restrict__ va1,
                        const float* __restrict__ W2, const float* __restrict__ b2,
                        const float* __restrict__ ga2, const float* __restrict__ be2,
                        const float* __restrict__ mu2, const float* __restrict__ va2) {
    int tid = threadIdx.x;
    float part = 0.f;
    if (blockIdx.x < N1) {
        int o = blockIdx.x;
        int nb = o >> 8, nlo = o & 255;
        size_t rowbase = (size_t)nb * B_TS + (size_t)nlo * 128;
        int nsw = nlo & 7;
        for (int k = tid; k < K1; k += 256) {
            float s = ga1[k] * rsqrtf(va1[k] + BN_EPS);
            float w = W1[(size_t)o * K1 + k];
            part += w * (be1[k] - mu1[k] * s);
            float wb = w * s;
            if (k < K1 - 96) {
                float s2 = ga1[k + 96] * rsqrtf(va1[k + 96] + BN_EPS);
                wb -= W1[(size_t)o * K1 + k + 96] * s2;
            }
            __half hi = __float2half_rn(wb);
            __half lo = __float2half_rn(wb - __half2float(hi));
            int ck = k >> 5, uh = (k >> 3) & 3, byo = (k & 7) * 2;
            size_t base = (size_t)ck * (2 * B_TS) + rowbase;
            *(__half*)(g_W1p + base + ((uh ^ nsw) << 4) + byo) = hi;
            *(__half*)(g_W1p + base + (((uh + 4) ^ nsw) << 4) + byo) = lo;
        }
    } else {
        int o = blockIdx.x - N1;
        for (int c = tid; c < N1; c += 256) {
            float s = ga2[c] * rsqrtf(va2[c] + BN_EPS);
            float w = W2[(size_t)o * N1 + c];
            part += w * (be2[c] - mu2[c] * s);
            float wf = w * s;
            __half hi = __float2half_rn(wf);
            g_W2h[(size_t)o * N1 + c] = hi;
            g_W2l[(size_t)o * N1 + c] = __float2half_rn(wf - __half2float(hi));
        }
    }
    __shared__ float red[256];
    red[tid] = part; __syncthreads();
    for (int s = 128; s > 0; s >>= 1) { if (tid < s) red[tid] += red[tid + s]; __syncthreads(); }
    if (tid == 0) {
        if (blockIdx.x < N1) g_b1f[blockIdx.x] = b1[blockIdx.x] + red[0];
        else g_b2f[blockIdx.x - N1] = b2[blockIdx.x - N1] + red[0];
    }
}

// -------------------- summed-area tables --------------------------------------
__global__ void k_sat_rows(const float* __restrict__ x) {
    int idx = blockIdx.x * blockDim.x + threadIdx.x;
    if (idx >= Bn * Cn * SATR) return;
    int img = idx / SATR, r = idx % SATR;
    float* S = g_sat + (size_t)img * SATR * SATC;
    if (r == 0) { for (int cx = 0; cx <= 128; cx++) S[cx] = 0.f; }
    else {
        const float* row = x + (size_t)img * HWn + (size_t)(r - 1) * Wn;
        float* Sr = S + (size_t)r * SATC;
        Sr[0] = 0.f;
        float acc = 0.f;
        for (int xx = 0; xx < Wn; xx++) { acc += row[xx]; Sr[xx + 1] = acc; }
    }
}
__global__ void k_sat_cols() {
    int idx = blockIdx.x * blockDim.x + threadIdx.x;
    if (idx >= Bn * Cn * SATR) return;
    int img = idx / SATR, cc = idx % SATR;
    float* S = g_sat + (size_t)img * SATR * SATC;
    float acc = 0.f;
    for (int r = 1; r <= 128; r++) {
        acc += S[(size_t)r * SATC + cc];
        S[(size_t)r * SATC + cc] = acc;
    }
}

// -------------------- features -> packed swizzled phi blocks ------------------
// Each thread: 2 consecutive pixels for one ring size j; inner loop over 96 ch.
__global__ void k_features(const float* __restrict__ x) {
    int j = blockIdx.y;                           // 0..12
    int m = blockIdx.x * 512 + threadIdx.x * 2;
    int b = m >> 14, pix = m & (HWn - 1), y = pix >> 7, xx = pix & 127;
    int mtile = m >> 7, mloc = m & 127;
    uint32_t ub = (uint32_t)(mloc >> 3);
    size_t outm = (size_t)mtile * ((size_t)NC1 * A_TS) + (size_t)(mloc & 7) * 2;

    if (j == 0) {
        const float* p = x + (size_t)b * Cn * HWn + pix;
        #pragma unroll 4
        for (int c = 0; c < 96; c++) {
            float v0 = p[(size_t)c * HWn], v1 = p[(size_t)c * HWn + 1];
            size_t off = outm + (size_t)(c >> 5) * A_TS + (size_t)(c & 31) * 256
                       + (size_t)((ub ^ (uint32_t)(c & 7)) << 4);
            *(__half2*)(g_phiB + off) = __floats2half2_rn(v0, v1);
        }
    } else {
        int rlo = max(y - j, 0), rhi = min(y + j + 1, 128);
        int cl0 = max(xx - j, 0), ch0 = min(xx + j + 1, 128);
        int cl1 = max(xx + 1 - j, 0), ch1 = min(xx + j + 2, 128);
        int ohh0 = rhi * SATC + ch0, olh0 = rlo * SATC + ch0;
        int ohl0 = rhi * SATC + cl0, oll0 = rlo * SATC + cl0;
        int ohh1 = rhi * SATC + ch1, olh1 = rlo * SATC + ch1;
        int ohl1 = rhi * SATC + cl1, oll1 = rlo * SATC + cl1;
        const float* Sb = g_sat + (size_t)b * Cn * (SATR * SATC);
        #pragma unroll 2
        for (int c = 0; c < 96; c++) {
            const float* S = Sb + (size_t)c * (SATR * SATC);
            float v0 = S[ohh0] - S[olh0] - S[ohl0] + S[oll0];
            float v1 = S[ohh1] - S[olh1] - S[ohl1] + S[oll1];
            int k = j * 96 + c;
            size_t off = outm + (size_t)(k >> 5) * A_TS + (size_t)(k & 31) * 256
                       + (size_t)((ub ^ (uint32_t)(k & 7)) << 4);
            *(__half2*)(g_phiB + off) = __floats2half2_rn(v0, v1);
        }
    }
}

// -------------------- GEMM1: bulk-staged, 4-stage mbarrier ring ---------------
// C[128m, 256n] per CTA, 8 warps (2m x 4n), warp tile 64x64.
__global__ void __launch_bounds__(256, 1) k_gemm1() {
    constexpr int OFF_BIAS = NSTG * STG;           // 163840
    constexpr int OFF_MBAR = OFF_BIAS + 1024;      // 164864
    extern __shared__ char smem[];
    uint32_t sb = smem_u32(smem);
    float* s_bias = (float*)(smem + OFF_BIAS);
    int tid = threadIdx.x, wid = tid >> 5, lane = tid & 31;
    int grp = lane >> 3, rr = lane & 7;
    int wm = (wid & 1) * 64, wn = (wid >> 1) * 64;
    int mtile = blockIdx.x, nb = blockIdx.y;
    int n0 = nb * 256;

    if (tid == 0) {
        #pragma unroll
        for (int s = 0; s < NSTG; s++) MBAR_INIT(sb + OFF_MBAR + s * 8, 1);
        asm volatile("fence.proxy.async.shared::cta;" ::: "memory");
    }
    for (int i = tid; i < 256; i += 256) s_bias[i] = g_b1f[n0 + i];
    __syncthreads();

    const uint8_t* phiB = g_phiB + (size_t)mtile * ((size_t)NC1 * A_TS);
    const uint8_t* w1p  = g_W1p + (size_t)nb * B_TS;

    if (tid == 0) {
        #pragma unroll
        for (int s = 0; s < NSTG; s++) {
            uint32_t mb = sb + OFF_MBAR + s * 8;
            MBAR_EXPECT_TX(mb, STG);
            bulk_g2s(sb + s * STG, phiB + (size_t)s * A_TS, A_TS, mb);
            bulk_g2s(sb + s * STG + A_TS, w1p + (size_t)s * (2 * B_TS), B_TS, mb);
        }
    }

    // precomputed fragment offsets (stage-relative)
    uint32_t aoff[2][4], bho[2][4], blo[2][4];
    #pragma unroll
    for (int ks = 0; ks < 2; ks++) {
        #pragma unroll
        for (int mt = 0; mt < 4; mt++) {
            int row = ks * 16 + (grp >> 1) * 8 + rr;
            int u = (wm >> 3) + mt * 2 + (grp & 1);
            aoff[ks][mt] = (uint32_t)(row * 256 + ((u ^ rr) << 4));
        }
        #pragma unroll
        for (int p = 0; p < 4; p++) {
            int n = wn + p * 16 + (grp >> 1) * 8 + rr;
            int uh = ks * 2 + (grp & 1);
            bho[ks][p] = (uint32_t)(n * 128 + ((uh ^ rr) << 4));
            blo[ks][p] = (uint32_t)(n * 128 + (((uh + 4) ^ rr) << 4));
        }
    }

    float acc[4][8][4];
    #pragma unroll
    for (int mt = 0; mt < 4; mt++)
        #pragma unroll
        for (int nt = 0; nt < 8; nt++)
            #pragma unroll
            for (int q = 0; q < 4; q++) acc[mt][nt][q] = 0.f;

    for (int c = 0; c < NC1; c++) {
        int s = c & (NSTG - 1);
        MBAR_WAIT(sb + OFF_MBAR + s * 8, (c >> 2) & 1);
        uint32_t bA = sb + s * STG, bB = bA + A_TS;
        #pragma unroll
        for (int ks = 0; ks < 2; ks++) {
            uint32_t ah[4][4], bh[8][2], bl[8][2];
            #pragma unroll
            for (int mt = 0; mt < 4; mt++)
                ldsm4t(ah[mt][0], ah[mt][1], ah[mt][2], ah[mt][3], bA + aoff[ks][mt]);
            #pragma unroll
            for (int p = 0; p < 4; p++) {
                ldsm4(bh[2*p][0], bh[2*p][1], bh[2*p+1][0], bh[2*p+1][1], bB + bho[ks][p]);
                ldsm4(bl[2*p][0], bl[2*p][1], bl[2*p+1][0], bl[2*p+1][1], bB + blo[ks][p]);
            }
            #pragma unroll
            for (int mt = 0; mt < 4; mt++)
                #pragma unroll
                for (int nt = 0; nt < 8; nt++) {
                    mma_h(acc[mt][nt], ah[mt], bh[nt]);
                    mma_h(acc[mt][nt], ah[mt], bl[nt]);
                }
        }
        __syncthreads();
        if (tid == 0 && c + NSTG < NC1) {
            uint32_t mb = sb + OFF_MBAR + s * 8;
            MBAR_EXPECT_TX(mb, STG);
            bulk_g2s(sb + s * STG, phiB + (size_t)(c + NSTG) * A_TS, A_TS, mb);
            bulk_g2s(sb + s * STG + A_TS, w1p + (size_t)(c + NSTG) * (2 * B_TS), B_TS, mb);
        }
    }

    // epilogue: relu(v + bias) -> h1 fp16 [m][N1]
    int g = lane >> 2, t = lane & 3;
    int m0 = mtile * 128;
    #pragma unroll
    for (int mt = 0; mt < 4; mt++) {
        int mr = m0 + wm + mt * 16 + g;
        #pragma unroll
        for (int nt = 0; nt < 8; nt++) {
            int ncl = wn + nt * 8 + 2 * t;
            #pragma unroll
            for (int h = 0; h < 2; h++) {
                int mrow = mr + h * 8;
                float v0 = fmaxf(acc[mt][nt][2 * h]     + s_bias[ncl], 0.f);
                float v1 = fmaxf(acc[mt][nt][2 * h + 1] + s_bias[ncl + 1], 0.f);
                *(__half2*)(g_h1 + (size_t)mrow * N1 + n0 + ncl) = __floats2half2_rn(v0, v1);
            }
        }
    }
}

// -------------------- GEMM2: C[128m, 96n], cp.async pipeline ------------------
__global__ void __launch_bounds__(256, 1) k_gemm2(float* __restrict__ dout) {
    constexpr int A_RS = 80, A_T2 = 128 * A_RS;
    constexpr int B_RS = 80, B_T2 = 96 * B_RS;
    constexpr int SS = A_T2 + 2 * B_T2;
    constexpr int NCk = N1 / 32;

    extern __shared__ char smem[];
    float* s_bias = (float*)(smem + 2 * SS);
    uint32_t sb = smem_u32(smem);
    int tid = threadIdx.x, wid = tid >> 5, lane = tid & 31;
    int wm = (wid & 3) * 32, wn = (wid >> 2) * 48;
    int m0 = blockIdx.x * 128;

    for (int i = tid; i < 96; i += 256) s_bias[i] = g_b2f[i];

    int grp = lane >> 3, r = lane & 7;
    uint32_t aoff0 = (uint32_t)((wm + (grp & 1) * 8 + r) * A_RS + (grp >> 1) * 16);
    uint32_t boff0 = (uint32_t)((wn + (grp >> 1) * 8 + r) * B_RS + (grp & 1) * 16);

    float acc[2][6][4];
    #pragma unroll
    for (int mt = 0; mt < 2; mt++)
        #pragma unroll
        for (int nt = 0; nt < 6; nt++)
            #pragma unroll
            for (int q = 0; q < 4; q++) acc[mt][nt][q] = 0.f;

    auto stage = [&](int c, int s) {
        uint32_t base = sb + s * SS;
        int kb = c * 32;
        #pragma unroll
        for (int i = tid; i < 512; i += 256) {
            int rr2 = i >> 2, u = i & 3;
            cpa16(base + rr2 * A_RS + u * 16, g_h1 + (size_t)(m0 + rr2) * N1 + kb + u * 8);
        }
        #pragma unroll
        for (int i = tid; i < 384; i += 256) {
            int rr2 = i >> 2, u = i & 3;
            size_t so = (size_t)rr2 * N1 + kb + u * 8;
            cpa16(base + A_T2 + rr2 * B_RS + u * 16, g_W2h + so);
            cpa16(base + A_T2 + B_T2 + rr2 * B_RS + u * 16, g_W2l + so);
        }
        asm volatile("cp.async.commit_group;" ::: "memory");
    };

    stage(0, 0);
    for (int c = 0; c < NCk; c++) {
        int s = c & 1;
        if (c + 1 < NCk) {
            stage(c + 1, s ^ 1);
            asm volatile("cp.async.wait_group 1;" ::: "memory");
        } else {
            asm volatile("cp.async.wait_group 0;" ::: "memory");
        }
        __syncthreads();

        uint32_t bA = sb + s * SS, bB = bA + A_T2;
        #pragma unroll
        for (int ks = 0; ks < 2; ks++) {
            uint32_t ah[2][4], bh[6][2], bl[6][2];
            #pragma unroll
            for (int mt = 0; mt < 2; mt++)
                ldsm4(ah[mt][0], ah[mt][1], ah[mt][2], ah[mt][3],
                      bA + aoff0 + mt * (16 * A_RS) + ks * 32);
            #pragma unroll
            for (int p = 0; p < 3; p++) {
                uint32_t off = boff0 + p * (16 * B_RS) + ks * 32;
                ldsm4(bh[2*p][0], bh[2*p][1], bh[2*p+1][0], bh[2*p+1][1], bB + off);
                ldsm4(bl[2*p][0], bl[2*p][1], bl[2*p+1][0], bl[2*p+1][1], bB + B_T2 + off);
            }
            #pragma unroll
            for (int mt = 0; mt < 2; mt++)
                #pragma unroll
                for (int nt = 0; nt < 6; nt++) {
                    mma_h(acc[mt][nt], ah[mt], bh[nt]);
                    mma_h(acc[mt][nt], ah[mt], bl[nt]);
                }
        }
        __syncthreads();
    }

    int g = lane >> 2, t = lane & 3;
    #pragma unroll
    for (int mt = 0; mt < 2; mt++) {
        int mr = m0 + wm + mt * 16 + g;
        #pragma unroll
        for (int nt = 0; nt < 6; nt++) {
            int nc = wn + nt * 8 + 2 * t;
            #pragma unroll
            for (int h = 0; h < 2; h++) {
                int mrow = mr + h * 8;
                int b = mrow >> 14, pix = mrow & (HWn - 1);
                dout[(size_t)(b * N2 + nc) * HWn + pix]     = acc[mt][nt][2 * h]     + s_bias[nc];
                dout[(size_t)(b * N2 + nc + 1) * HWn + pix] = acc[mt][nt][2 * h + 1] + s_bias[nc + 1];
            }
        }
    }
}

// -------------------- launch ------------------------------------------------
extern "C" void kernel_launch(void* const* d_in, const int* in_sizes, int n_in,
                              void* d_out, int out_size) {
    (void)in_sizes; (void)n_in; (void)out_size;
    const float* x   = (const float*)d_in[0];
    const float* g1  = (const float*)d_in[1];
    const float* be1 = (const float*)d_in[2];
    const float* mu1 = (const float*)d_in[3];
    const float* va1 = (const float*)d_in[4];
    const float* W1  = (const float*)d_in[5];
    const float* b1  = (const float*)d_in[6];
    const float* g2  = (const float*)d_in[7];
    const float* be2 = (const float*)d_in[8];
    const float* mu2 = (const float*)d_in[9];
    const float* va2 = (const float*)d_in[10];
    const float* W2  = (const float*)d_in[11];
    const float* b2  = (const float*)d_in[12];

    constexpr int S1 = NSTG * STG + 1024 + NSTG * 8 + 32;             // ~165 KB
    constexpr int S2 = 2 * (128 * 80 + 2 * 96 * 80) + 96 * 4;         // 51.6 KB
    cudaFuncSetAttribute(k_gemm1, cudaFuncAttributeMaxDynamicSharedMemorySize, S1);
    cudaFuncSetAttribute(k_gemm2, cudaFuncAttributeMaxDynamicSharedMemorySize, S2);

    k_folds<<<N1 + N2, 256>>>(W1, b1, g1, be1, mu1, va1, W2, b2, g2, be2, mu2, va2);

    int nsat = Bn * Cn * SATR;
    k_sat_rows<<<(nsat + 127) / 128, 128>>>(x);
    k_sat_cols<<<(nsat + 127) / 128, 128>>>();

    k_features<<<dim3(Mtot / 512, 13), 256>>>(x);

    k_gemm1<<<dim3(Mtot / 128, 2), 256, S1>>>();
    k_gemm2<<<dim3(Mtot / 128, 1), 256, S2>>>((float*)d_out);
}